// round 2
// baseline (speedup 1.0000x reference)
#include <cuda_runtime.h>
#include <cuda_bf16.h>
#include <cstdint>

// Problem constants (fixed by the dataset)
#define MAXN 50000
#define IN_DIM 128
#define HID 96
// OUT=2, masked output = column 1

// Scratch (static device globals -- no runtime allocation allowed)
__device__ float g_dinv[MAXN];          // degree -> dinv in place
__device__ float g_z[MAXN * HID];       // GEMM outputs
__device__ float g_p[MAXN * HID];       // propagation outputs

// ---------------------------------------------------------------------------
// Degree / dinv   (edge_index delivered as int32: [2, E] flattened)
// ---------------------------------------------------------------------------
__global__ void k_deg_init(float* deg, int n) {
    int i = blockIdx.x * blockDim.x + threadIdx.x;
    if (i < n) deg[i] = 1.0f;  // self loop
}

__global__ void k_deg_scatter(const int* __restrict__ ei, int E, float* deg) {
    int e = blockIdx.x * blockDim.x + threadIdx.x;
    if (e >= E) return;
    int d = ei[E + e];  // dst row
    atomicAdd(&deg[d], 1.0f);
}

__global__ void k_dinv(float* deg, int n) {
    int i = blockIdx.x * blockDim.x + threadIdx.x;
    if (i < n) deg[i] = rsqrtf(deg[i]);
}

// ---------------------------------------------------------------------------
// GEMM: out[n x HID] = f(A)[n x K] @ W[K x HID]
// MODE 0: f(a) = (a - t1[k]) / t2[k]          (standard scaler, layer 1)
// MODE 1: f(a) = max(a + t1[k], 0)            (bias + relu, layers 2/3)
// Tile: 64 rows x 96 cols, 256 threads (8 warps). Warp w owns rows w*8..w*8+7,
// lane l owns cols {l, l+32, l+64}. K is chunked by 32 through shared memory.
// ---------------------------------------------------------------------------
template <int K, int MODE>
__global__ void __launch_bounds__(256)
k_gemm(const float* __restrict__ A, const float* __restrict__ W,
       const float* __restrict__ t1, const float* __restrict__ t2,
       float* __restrict__ out, int n)
{
    __shared__ float As[64 * 32];
    __shared__ float Ws[32 * HID];

    const int tid = threadIdx.x;
    const int w = tid >> 5;
    const int l = tid & 31;
    const int row0 = blockIdx.x * 64;

    float acc[8][3];
#pragma unroll
    for (int r = 0; r < 8; r++) { acc[r][0] = acc[r][1] = acc[r][2] = 0.f; }

    for (int kc = 0; kc < K; kc += 32) {
        // Load W chunk [32 x 96], coalesced.
        for (int i = tid; i < 32 * HID; i += 256) {
            int kk = i / HID;
            int c = i - kk * HID;
            Ws[i] = W[(size_t)(kc + kk) * HID + c];
        }
        // Load A chunk [64 x 32], coalesced over k, with operand transform.
        for (int i = tid; i < 64 * 32; i += 256) {
            int r = i >> 5;
            int kk = i & 31;
            int grow = row0 + r;
            int k = kc + kk;
            float v = 0.f;
            if (grow < n) {
                v = A[(size_t)grow * K + k];
                if (MODE == 0)      v = (v - t1[k]) / t2[k];
                else                v = fmaxf(v + t1[k], 0.f);
            }
            As[i] = v;
        }
        __syncthreads();

#pragma unroll
        for (int kk = 0; kk < 32; kk++) {
            float w0 = Ws[kk * HID + l];
            float w1 = Ws[kk * HID + l + 32];
            float w2 = Ws[kk * HID + l + 64];
#pragma unroll
            for (int r = 0; r < 8; r++) {
                float a = As[(w * 8 + r) * 32 + kk];  // smem broadcast
                acc[r][0] = fmaf(a, w0, acc[r][0]);
                acc[r][1] = fmaf(a, w1, acc[r][1]);
                acc[r][2] = fmaf(a, w2, acc[r][2]);
            }
        }
        __syncthreads();
    }

#pragma unroll
    for (int r = 0; r < 8; r++) {
        int grow = row0 + w * 8 + r;
        if (grow < n) {
            float* o = out + (size_t)grow * HID;
            o[l]      = acc[r][0];
            o[l + 32] = acc[r][1];
            o[l + 64] = acc[r][2];
        }
    }
}

// ---------------------------------------------------------------------------
// Propagation: p[v] = dinv[v]^2 * z[v]  +  sum_{e: dst=v} dinv[src]*dinv[v]*z[src]
// ---------------------------------------------------------------------------
__global__ void k_prop_init(const float* __restrict__ dinv,
                            const float* __restrict__ z,
                            float* __restrict__ p, int n)
{
    int i = blockIdx.x * blockDim.x + threadIdx.x;   // over n*24 float4s
    if (i >= n * (HID / 4)) return;
    int v = i / (HID / 4);
    float di = dinv[v];
    float wgt = di * di;
    float4 val = reinterpret_cast<const float4*>(z)[i];
    val.x *= wgt; val.y *= wgt; val.z *= wgt; val.w *= wgt;
    reinterpret_cast<float4*>(p)[i] = val;
}

__device__ __forceinline__ void red_add_v4(float* addr, float4 v) {
    asm volatile("red.global.add.v4.f32 [%0], {%1,%2,%3,%4};"
                 :: "l"(addr), "f"(v.x), "f"(v.y), "f"(v.z), "f"(v.w)
                 : "memory");
}

// 8 threads per edge; each handles 12 floats (3x float4) of the 96-float row.
__global__ void __launch_bounds__(256)
k_prop_scatter(const int* __restrict__ ei, int E,
               const float* __restrict__ dinv,
               const float* __restrict__ z,
               float* __restrict__ p)
{
    int t = blockIdx.x * blockDim.x + threadIdx.x;
    int e = t >> 3;
    int part = t & 7;
    if (e >= E) return;
    int s = ei[e];
    int d = ei[E + e];
    float wgt = dinv[s] * dinv[d];
    const float4* zs = reinterpret_cast<const float4*>(z + (size_t)s * HID + part * 12);
    float* pd = p + (size_t)d * HID + part * 12;
#pragma unroll
    for (int j = 0; j < 3; j++) {
        float4 v = zs[j];
        v.x *= wgt; v.y *= wgt; v.z *= wgt; v.w *= wgt;
        red_add_v4(pd + j * 4, v);
    }
}

// ---------------------------------------------------------------------------
// Final: out[i] = bout[1] + sum_k (p[i,k] + b3[k]) * Wout[k,1]
// One warp per node; lane l covers k = l, l+32, l+64.
// ---------------------------------------------------------------------------
__global__ void __launch_bounds__(256)
k_final(const float* __restrict__ p, const float* __restrict__ b3,
        const float* __restrict__ Wout, const float* __restrict__ bout,
        float* __restrict__ out, int n)
{
    int gt = blockIdx.x * blockDim.x + threadIdx.x;
    int v = gt >> 5;
    int l = gt & 31;
    if (v >= n) return;
    float acc = 0.f;
#pragma unroll
    for (int t = 0; t < 3; t++) {
        int k = l + 32 * t;
        acc = fmaf(p[(size_t)v * HID + k] + b3[k], Wout[2 * k + 1], acc);
    }
#pragma unroll
    for (int off = 16; off; off >>= 1)
        acc += __shfl_xor_sync(0xffffffffu, acc, off);
    if (l == 0) out[v] = acc + bout[1];
}

// ---------------------------------------------------------------------------
// Host launch
// ---------------------------------------------------------------------------
extern "C" void kernel_launch(void* const* d_in, const int* in_sizes, int n_in,
                              void* d_out, int out_size)
{
    const float* x     = (const float*)d_in[0];
    const int*   ei    = (const int*)d_in[1];     // int64 in JAX -> int32 delivery
    // d_in[2] = PQVA_mask (deterministic: column 0 masked -> output is column 1)
    const float* mean  = (const float*)d_in[3];
    const float* stdv  = (const float*)d_in[4];
    const float* W1    = (const float*)d_in[5];
    const float* b1    = (const float*)d_in[6];
    const float* W2    = (const float*)d_in[7];
    const float* b2    = (const float*)d_in[8];
    const float* W3    = (const float*)d_in[9];
    const float* b3    = (const float*)d_in[10];
    const float* Wout  = (const float*)d_in[11];
    const float* bout  = (const float*)d_in[12];
    float* out = (float*)d_out;

    const int N = in_sizes[0] / IN_DIM;
    const int E = in_sizes[1] / 2;

    float *dinv, *z, *p;
    cudaGetSymbolAddress((void**)&dinv, g_dinv);
    cudaGetSymbolAddress((void**)&z,    g_z);
    cudaGetSymbolAddress((void**)&p,    g_p);

    const int TB = 256;
    int nb_n    = (N + TB - 1) / TB;
    int nb_e    = (E + TB - 1) / TB;
    int nb_gemm = (N + 63) / 64;
    int nb_pi   = (N * (HID / 4) + TB - 1) / TB;
    int nb_sc   = (E * 8 + TB - 1) / TB;
    int nb_fin  = (N * 32 + TB - 1) / TB;

    // Degree + dinv
    k_deg_init<<<nb_n, TB>>>(dinv, N);
    k_deg_scatter<<<nb_e, TB>>>(ei, E, dinv);
    k_dinv<<<nb_n, TB>>>(dinv, N);

    // Layer 1: z = ((x - mean)/std) @ W1 ; p = prop(z)
    k_gemm<IN_DIM, 0><<<nb_gemm, TB>>>(x, W1, mean, stdv, z, N);
    k_prop_init<<<nb_pi, TB>>>(dinv, z, p, N);
    k_prop_scatter<<<nb_sc, TB>>>(ei, E, dinv, z, p);

    // Layer 2: z = relu(p + b1) @ W2 ; p = prop(z)
    k_gemm<HID, 1><<<nb_gemm, TB>>>(p, W2, b1, nullptr, z, N);
    k_prop_init<<<nb_pi, TB>>>(dinv, z, p, N);
    k_prop_scatter<<<nb_sc, TB>>>(ei, E, dinv, z, p);

    // Layer 3: z = relu(p + b2) @ W3 ; p = prop(z)
    k_gemm<HID, 1><<<nb_gemm, TB>>>(p, W3, b2, nullptr, z, N);
    k_prop_init<<<nb_pi, TB>>>(dinv, z, p, N);
    k_prop_scatter<<<nb_sc, TB>>>(ei, E, dinv, z, p);

    // Final: out[i] = (p[i] + b3) . Wout[:,1] + bout[1]
    k_final<<<nb_fin, TB>>>(p, b3, Wout, bout, out, N);
}

// round 3
// speedup vs baseline: 1.6446x; 1.6446x over previous
#include <cuda_runtime.h>
#include <cuda_bf16.h>
#include <cstdint>

#define MAXN 50000
#define IN_DIM 128
#define HID 96
#define EMAX 1048576

// Static scratch (no runtime allocation allowed)
__device__ __align__(16) float g_z[MAXN * HID];   // GEMM outputs (pre-scaled by dinv)
__device__ __align__(16) float g_h[MAXN * HID];   // gather outputs (bias+relu applied)
__device__ float g_dinv[MAXN];
__device__ float g_invstd[IN_DIM];
__device__ int   g_cnt[MAXN];
__device__ int   g_rowptr[MAXN + 1];
__device__ int   g_cursor[MAXN];
__device__ int   g_col[EMAX];

// ---------------------------------------------------------------------------
// CSR build
// ---------------------------------------------------------------------------
__global__ void k_zero(int* cnt, int n) {
    int i = blockIdx.x * blockDim.x + threadIdx.x;
    if (i < n) cnt[i] = 0;
}

__global__ void k_count(const int* __restrict__ ei, int E, int* cnt) {
    int e = blockIdx.x * blockDim.x + threadIdx.x;
    if (e < E) atomicAdd(&cnt[ei[E + e]], 1);
}

// Single-block scan (1024 threads): rowptr (exclusive on cnt), cursor=rowptr copy,
// dinv = rsqrt(cnt+1)  (+1 = self loop).
__global__ void k_scan(const int* __restrict__ cnt, int* __restrict__ rowptr,
                       int* __restrict__ cursor, float* __restrict__ dinv, int n)
{
    __shared__ int warp_sums[32];
    __shared__ int s_carry;
    int tid = threadIdx.x, lane = tid & 31, wid = tid >> 5;
    if (tid == 0) { s_carry = 0; rowptr[0] = 0; }
    __syncthreads();
    for (int base = 0; base < n; base += 1024) {
        int i = base + tid;
        int v = (i < n) ? cnt[i] : 0;
        int x = v;
#pragma unroll
        for (int d = 1; d < 32; d <<= 1) {
            int t = __shfl_up_sync(~0u, x, d);
            if (lane >= d) x += t;
        }
        if (lane == 31) warp_sums[wid] = x;
        __syncthreads();
        if (wid == 0) {
            int ws = warp_sums[lane];
#pragma unroll
            for (int d = 1; d < 32; d <<= 1) {
                int t = __shfl_up_sync(~0u, ws, d);
                if (lane >= d) ws += t;
            }
            warp_sums[lane] = ws;
        }
        __syncthreads();
        int incl = x + (wid > 0 ? warp_sums[wid - 1] : 0) + s_carry;
        if (i < n) {
            rowptr[i + 1] = incl;
            cursor[i]     = incl - v;
            dinv[i]       = rsqrtf((float)(cnt[i] + 1));
        }
        __syncthreads();
        if (tid == 1023) s_carry = incl;
        __syncthreads();
    }
}

__global__ void k_fill(const int* __restrict__ ei, int E,
                       int* __restrict__ cursor, int* __restrict__ col)
{
    int e = blockIdx.x * blockDim.x + threadIdx.x;
    if (e >= E) return;
    int s = ei[e], d = ei[E + e];
    int slot = atomicAdd(&cursor[d], 1);
    col[slot] = s;
}

__global__ void k_prep(const float* __restrict__ stdv, float* __restrict__ invstd) {
    int i = threadIdx.x;
    if (i < IN_DIM) invstd[i] = 1.0f / stdv[i];
}

// ---------------------------------------------------------------------------
// GEMM: out[n x 96] = f(A)[n x K] @ W[K x 96], epilogue out *= dinv[row].
// SCALER: f(a) = (a - mean[k]) * invstd[k]; else identity.
// Block tile 128 rows x 96 cols, 256 threads, thread tile 8x6.
// As staged transposed [kk][row] (stride 132, float4-aligned), Ws [kk][col].
// ---------------------------------------------------------------------------
template <int K, bool SCALER>
__global__ void __launch_bounds__(256, 3)
k_gemm(const float* __restrict__ A, const float* __restrict__ W,
       const float* __restrict__ mean, const float* __restrict__ invstd,
       const float* __restrict__ dinv, float* __restrict__ out, int n)
{
    constexpr int KC = 32;
    __shared__ float As[KC * 132];
    __shared__ float Ws[KC * 96];

    const int tid = threadIdx.x;
    const int tx = tid & 15;    // cols tx*6 .. tx*6+5
    const int ty = tid >> 4;    // rows ty*8 .. ty*8+7
    const int row0 = blockIdx.x * 128;

    const int lrow  = tid >> 1;  // A-load row 0..127
    const int lhalf = tid & 1;   // k half (16 values)

    float acc[8][6];
#pragma unroll
    for (int r = 0; r < 8; r++)
#pragma unroll
        for (int c = 0; c < 6; c++) acc[r][c] = 0.f;

    const int grow_l = row0 + lrow;
    const bool okl = grow_l < n;

#pragma unroll 1
    for (int kc = 0; kc < K; kc += KC) {
        // W chunk [32 x 96], coalesced
#pragma unroll
        for (int i = tid; i < KC * 96; i += 256)
            Ws[i] = W[(size_t)(kc + i / 96) * 96 + (i % 96)];
        // A chunk, transposed, with optional scaler transform
        const float* Ap = A + (size_t)grow_l * K + kc + lhalf * 16;
#pragma unroll
        for (int j = 0; j < 4; j++) {
            float4 v = okl ? *(const float4*)(Ap + j * 4) : make_float4(0.f, 0.f, 0.f, 0.f);
            int k0 = lhalf * 16 + j * 4;
            if (SCALER) {
                int kg = kc + k0;
                v.x = (v.x - mean[kg + 0]) * invstd[kg + 0];
                v.y = (v.y - mean[kg + 1]) * invstd[kg + 1];
                v.z = (v.z - mean[kg + 2]) * invstd[kg + 2];
                v.w = (v.w - mean[kg + 3]) * invstd[kg + 3];
            }
            As[(k0 + 0) * 132 + lrow] = v.x;
            As[(k0 + 1) * 132 + lrow] = v.y;
            As[(k0 + 2) * 132 + lrow] = v.z;
            As[(k0 + 3) * 132 + lrow] = v.w;
        }
        __syncthreads();

#pragma unroll 8
        for (int kk = 0; kk < KC; kk++) {
            float4 a0 = *(const float4*)&As[kk * 132 + ty * 8];
            float4 a1 = *(const float4*)&As[kk * 132 + ty * 8 + 4];
            float w_[6];
#pragma unroll
            for (int c = 0; c < 6; c++) w_[c] = Ws[kk * 96 + tx * 6 + c];
            float a_[8] = {a0.x, a0.y, a0.z, a0.w, a1.x, a1.y, a1.z, a1.w};
#pragma unroll
            for (int r = 0; r < 8; r++)
#pragma unroll
                for (int c = 0; c < 6; c++)
                    acc[r][c] = fmaf(a_[r], w_[c], acc[r][c]);
        }
        __syncthreads();
    }

#pragma unroll
    for (int r = 0; r < 8; r++) {
        int grow = row0 + ty * 8 + r;
        if (grow < n) {
            float dv = dinv[grow];
            float* o = out + (size_t)grow * HID + tx * 6;
#pragma unroll
            for (int c = 0; c < 6; c++) o[c] = dv * acc[r][c];
        }
    }
}

// ---------------------------------------------------------------------------
// Gather (CSR): p[v] = dinv[v] * (sum_{s in N(v)} z'[s] + z'[v]),  z' = dinv*z.
// 8 threads per node, each owns 12 channels (3x float4).
// Epilogue: h = relu(p + bias), stored for next GEMM.
// ---------------------------------------------------------------------------
__device__ __forceinline__ void f4add(float4& a, const float4 b) {
    a.x += b.x; a.y += b.y; a.z += b.z; a.w += b.w;
}

__global__ void __launch_bounds__(256)
k_gather_br(const int* __restrict__ rowptr, const int* __restrict__ col,
            const float* __restrict__ dinv, const float* __restrict__ z,
            const float* __restrict__ bias, float* __restrict__ h, int n)
{
    int t = blockIdx.x * blockDim.x + threadIdx.x;
    int v = t >> 3, part = t & 7;
    if (v >= n) return;
    int beg = rowptr[v], end = rowptr[v + 1];
    const float4* self = (const float4*)(z + (size_t)v * HID + part * 12);
    float4 a0 = self[0], a1 = self[1], a2 = self[2];
    int j = beg;
    for (; j + 1 < end; j += 2) {
        int s0 = col[j], s1 = col[j + 1];
        const float4* z0 = (const float4*)(z + (size_t)s0 * HID + part * 12);
        const float4* z1 = (const float4*)(z + (size_t)s1 * HID + part * 12);
        float4 b0 = z0[0], b1 = z0[1], b2 = z0[2];
        float4 c0 = z1[0], c1 = z1[1], c2 = z1[2];
        f4add(a0, b0); f4add(a1, b1); f4add(a2, b2);
        f4add(a0, c0); f4add(a1, c1); f4add(a2, c2);
    }
    if (j < end) {
        int s0 = col[j];
        const float4* z0 = (const float4*)(z + (size_t)s0 * HID + part * 12);
        f4add(a0, z0[0]); f4add(a1, z0[1]); f4add(a2, z0[2]);
    }
    float dv = dinv[v];
    int kb = part * 12;
    float4 o0, o1, o2;
    o0.x = fmaxf(fmaf(dv, a0.x, bias[kb + 0]), 0.f);
    o0.y = fmaxf(fmaf(dv, a0.y, bias[kb + 1]), 0.f);
    o0.z = fmaxf(fmaf(dv, a0.z, bias[kb + 2]), 0.f);
    o0.w = fmaxf(fmaf(dv, a0.w, bias[kb + 3]), 0.f);
    o1.x = fmaxf(fmaf(dv, a1.x, bias[kb + 4]), 0.f);
    o1.y = fmaxf(fmaf(dv, a1.y, bias[kb + 5]), 0.f);
    o1.z = fmaxf(fmaf(dv, a1.z, bias[kb + 6]), 0.f);
    o1.w = fmaxf(fmaf(dv, a1.w, bias[kb + 7]), 0.f);
    o2.x = fmaxf(fmaf(dv, a2.x, bias[kb + 8]), 0.f);
    o2.y = fmaxf(fmaf(dv, a2.y, bias[kb + 9]), 0.f);
    o2.z = fmaxf(fmaf(dv, a2.z, bias[kb + 10]), 0.f);
    o2.w = fmaxf(fmaf(dv, a2.w, bias[kb + 11]), 0.f);
    float4* hp = (float4*)(h + (size_t)v * HID + kb);
    hp[0] = o0; hp[1] = o1; hp[2] = o2;
}

// Final gather fused with the output Linear (only column 1 survives the mask):
// out[v] = sum_k (dinv[v]*(acc+self)_k + b3_k) * Wout[k,1] + bout[1]
__global__ void __launch_bounds__(256)
k_gather_final(const int* __restrict__ rowptr, const int* __restrict__ col,
               const float* __restrict__ dinv, const float* __restrict__ z,
               const float* __restrict__ b3, const float* __restrict__ Wout,
               const float* __restrict__ bout, float* __restrict__ out, int n)
{
    int t = blockIdx.x * blockDim.x + threadIdx.x;
    int v = t >> 3, part = t & 7;
    if (v >= n) return;
    int beg = rowptr[v], end = rowptr[v + 1];
    const float4* self = (const float4*)(z + (size_t)v * HID + part * 12);
    float4 a0 = self[0], a1 = self[1], a2 = self[2];
    int j = beg;
    for (; j + 1 < end; j += 2) {
        int s0 = col[j], s1 = col[j + 1];
        const float4* z0 = (const float4*)(z + (size_t)s0 * HID + part * 12);
        const float4* z1 = (const float4*)(z + (size_t)s1 * HID + part * 12);
        float4 b0 = z0[0], b1 = z0[1], b2 = z0[2];
        float4 c0 = z1[0], c1 = z1[1], c2 = z1[2];
        f4add(a0, b0); f4add(a1, b1); f4add(a2, b2);
        f4add(a0, c0); f4add(a1, c1); f4add(a2, c2);
    }
    if (j < end) {
        int s0 = col[j];
        const float4* z0 = (const float4*)(z + (size_t)s0 * HID + part * 12);
        f4add(a0, z0[0]); f4add(a1, z0[1]); f4add(a2, z0[2]);
    }
    float dv = dinv[v];
    int kb = part * 12;
    float p[12] = {a0.x, a0.y, a0.z, a0.w, a1.x, a1.y, a1.z, a1.w,
                   a2.x, a2.y, a2.z, a2.w};
    float acc = 0.f;
#pragma unroll
    for (int i = 0; i < 12; i++) {
        int k = kb + i;
        acc = fmaf(fmaf(dv, p[i], b3[k]), Wout[2 * k + 1], acc);
    }
#pragma unroll
    for (int off = 4; off; off >>= 1)
        acc += __shfl_xor_sync(0xffffffffu, acc, off);
    if (part == 0) out[v] = acc + bout[1];
}

// ---------------------------------------------------------------------------
// Host launch
// ---------------------------------------------------------------------------
extern "C" void kernel_launch(void* const* d_in, const int* in_sizes, int n_in,
                              void* d_out, int out_size)
{
    const float* x    = (const float*)d_in[0];
    const int*   ei   = (const int*)d_in[1];     // int64 in JAX -> int32 delivery
    // d_in[2] = PQVA_mask (deterministic: output = column 1)
    const float* mean = (const float*)d_in[3];
    const float* stdv = (const float*)d_in[4];
    const float* W1   = (const float*)d_in[5];
    const float* b1   = (const float*)d_in[6];
    const float* W2   = (const float*)d_in[7];
    const float* b2   = (const float*)d_in[8];
    const float* W3   = (const float*)d_in[9];
    const float* b3   = (const float*)d_in[10];
    const float* Wout = (const float*)d_in[11];
    const float* bout = (const float*)d_in[12];
    float* out = (float*)d_out;

    const int N = in_sizes[0] / IN_DIM;
    const int E = in_sizes[1] / 2;

    float *z, *h, *dinv, *invstd;
    int *cnt, *rowptr, *cursor, *colb;
    cudaGetSymbolAddress((void**)&z, g_z);
    cudaGetSymbolAddress((void**)&h, g_h);
    cudaGetSymbolAddress((void**)&dinv, g_dinv);
    cudaGetSymbolAddress((void**)&invstd, g_invstd);
    cudaGetSymbolAddress((void**)&cnt, g_cnt);
    cudaGetSymbolAddress((void**)&rowptr, g_rowptr);
    cudaGetSymbolAddress((void**)&cursor, g_cursor);
    cudaGetSymbolAddress((void**)&colb, g_col);

    const int TB = 256;
    int nb_n = (N + TB - 1) / TB;
    int nb_e = (E + TB - 1) / TB;
    int nb_gemm = (N + 127) / 128;
    int nb_g = (N * 8 + TB - 1) / TB;

    // CSR build + dinv + invstd
    k_zero<<<nb_n, TB>>>(cnt, N);
    k_count<<<nb_e, TB>>>(ei, E, cnt);
    k_scan<<<1, 1024>>>(cnt, rowptr, cursor, dinv, N);
    k_prep<<<1, 128>>>(stdv, invstd);
    k_fill<<<nb_e, TB>>>(ei, E, cursor, colb);

    // Layer 1
    k_gemm<IN_DIM, true><<<nb_gemm, TB>>>(x, W1, mean, invstd, dinv, z, N);
    k_gather_br<<<nb_g, TB>>>(rowptr, colb, dinv, z, b1, h, N);
    // Layer 2
    k_gemm<HID, false><<<nb_gemm, TB>>>(h, W2, nullptr, nullptr, dinv, z, N);
    k_gather_br<<<nb_g, TB>>>(rowptr, colb, dinv, z, b2, h, N);
    // Layer 3 + fused output head
    k_gemm<HID, false><<<nb_gemm, TB>>>(h, W3, nullptr, nullptr, dinv, z, N);
    k_gather_final<<<nb_g, TB>>>(rowptr, colb, dinv, z, b3, Wout, bout, out, N);
}